// round 12
// baseline (speedup 1.0000x reference)
#include <cuda_runtime.h>
#include <cstdint>

#define NN 100
#define DD 128
#define CH 2048
#define NEG_INF __int_as_float(0xff800000)

// scratch per batch (floats): K[128][104]@0  V[128][108]@13312  P[100][132]@27136  Q[100][132]@40336
#define OFF_K 0
#define OFF_V 13312
#define OFF_P 27136
#define OFF_Q 40336
#define TBLK  53536

struct Args { const void* p[10]; long sz[10]; int n; int batch; };

__device__ float g_scr[(size_t)CH * TBLK];   // ~438MB, zero-init
__device__ int g_psel, g_klen, g_ok, g_enc, g_widx[5];

// ---------------- f32x2 helpers ----------------
__device__ __forceinline__ void ffma2(unsigned long long &d, unsigned long long a, unsigned long long b){
    asm("fma.rn.f32x2 %0, %1, %2, %0;" : "+l"(d) : "l"(a), "l"(b));
}
__device__ __forceinline__ unsigned long long dup2(float x){
    unsigned long long r; asm("mov.b64 %0, {%1, %1};" : "=l"(r) : "f"(x)); return r;
}
__device__ __forceinline__ void unpack2(unsigned long long v, float &lo, float &hi){
    asm("mov.b64 {%0, %1}, %2;" : "=f"(lo), "=f"(hi) : "l"(v));
}

// =====================================================================
// prep: device-side role detection by content. (proven)
// =====================================================================
__global__ void prep_kernel(Args a)
{
    if (threadIdx.x != 0) return;
    int ok = 1;

    int encIdx = 0; long mxs = -1;
    for (int i = 0; i < a.n; i++) if (a.sz[i] > mxs){ mxs = a.sz[i]; encIdx = i; }
    const long want = (long)a.batch * NN * DD;
    long scale = 1;
    if      (mxs == want)     scale = 1;
    else if (mxs == want * 4) scale = 4;
    else ok = 0;

    int psel = -1;
    for (int i = 0; i < a.n; i++){
        if (a.sz[i] / scale < 64) continue;
        const int* q = (const int*)a.p[i];
        bool good = true; int mn = 1 << 30, mxv = -1;
        for (int k = 0; k < 64; k++){
            const int v = q[k];
            if (v < 0 || v >= NN){ good = false; break; }
            mn = v < mn ? v : mn; mxv = v > mxv ? v : mxv;
        }
        if (good && mxv > mn){ psel = i; break; }
    }
    int klen = 10;
    if (psel >= 0 && a.batch > 0){
        const long kl = (a.sz[psel] / scale) / a.batch;
        if (kl >= 1 && kl <= NN) klen = (int)kl; else ok = 0;
    } else ok = 0;

    int prob = -1;
    for (int i = 0; i < a.n; i++){
        if (i == encIdx || i == psel) continue;
        if (a.sz[i] / scale == (long)DD * DD) continue;
        const float* f = (const float*)a.p[i];
        bool good = true;
        for (int k = 0; k < 64; k++){
            const float v = f[k];
            if (!(v > 0.f && v < 1.f)){ good = false; break; }
        }
        if (good){ prob = i; break; }
    }

    int w[10]; int nw = 0;
    for (int i = 0; i < a.n; i++)
        if (a.sz[i] / scale == (long)DD * DD && nw < 10) w[nw++] = i;
    if (nw != 5){ ok = 0; w[0]=2; w[1]=3; w[2]=4; w[3]=5; w[4]=6; }

    const bool dict = (prob < 0) ? true : (prob < encIdx);
    // roles: 0=Wq_first 1=Wq_last 2=Wk 3=Wv 4=Wcomb
    if (dict){ g_widx[0]=w[0]; g_widx[1]=w[1]; g_widx[2]=w[2]; g_widx[3]=w[3]; g_widx[4]=w[4]; }
    else     { g_widx[0]=w[2]; g_widx[1]=w[3]; g_widx[2]=w[1]; g_widx[3]=w[4]; g_widx[4]=w[0]; }

    g_psel = psel; g_klen = klen; g_enc = encIdx; g_ok = ok;
}

__global__ void prefill_kernel(Args a, float* __restrict__ out)
{
    const int b = blockIdx.x, tid = threadIdx.x;
    for (int j = tid; j < NN; j += blockDim.x) out[b*NN + j] = 1.0f;
    const int psel = g_psel, klen = g_klen;
    if (psel >= 0 && tid < klen){
        const int* pre = (const int*)a.p[psel];
        int p = pre[b*klen + tid];
        out[b*NN + tid] = (float)((p >= 0 && p < NN) ? p : 0);
    }
}

// =====================================================================
// gemm: grid (chunk, 4); 256 threads; f32x2 FMA core. (proven R10)
// =====================================================================
__global__ __launch_bounds__(256, 2) void gemm_kernel(Args a, int c0)
{
    if (!g_ok) return;
    __shared__ __align__(16) float Es[32*102 + 16];
    __shared__ __align__(16) float Ws[32*132];
    __shared__ __align__(16) float q1s[128];

    const int bb = blockIdx.x, m = blockIdx.y;
    const int b = c0 + bb;
    const int tid = threadIdx.x;
    const int tx = tid & 31;
    const int ty = tid >> 5;

    const int role = (m==0) ? 2 : (m==1) ? 1 : (m==2) ? 3 : 4;
    const float* W   = (const float*)a.p[g_widx[role]];
    const float* enc = (const float*)a.p[g_enc];
    const float* Eb  = enc + (size_t)b * (NN*DD);
    const int klen = g_klen;

    if (m == 1 && tid < 128){
        const int* pre = (const int*)a.p[g_psel];
        int last = pre[b*klen + (klen-1)];
        last = (last >= 0 && last < NN) ? last : 0;
        const float* er = Eb + last*DD;
        const float* Wqf = (const float*)a.p[g_widx[0]];
        float s = 0.f;
        for (int d = 0; d < DD; d++) s += er[d] * Wqf[d*DD + tid];
        q1s[tid] = s;
    }

    unsigned long long acc[7][4];
    #pragma unroll
    for (int k = 0; k < 7; k++){ acc[k][0]=0ull; acc[k][1]=0ull; acc[k][2]=0ull; acc[k][3]=0ull; }

    for (int dch = 0; dch < 4; dch++){
        const int d0 = dch * 32;
        __syncthreads();
        for (int e = tid; e < 3200; e += 256){
            const int n = e >> 5, dd = e & 31;
            Es[dd*102 + n] = Eb[n*DD + d0 + dd];
        }
        if (m < 3){
            for (int e = tid; e < 4096; e += 256){
                const int dd = e >> 7, c = e & 127;
                Ws[dd*132 + c] = W[(d0+dd)*DD + c];
            }
        } else {
            for (int e = tid; e < 4096; e += 256){
                const int c = e >> 5, dd = e & 31;
                Ws[dd*132 + c] = W[c*DD + d0 + dd];
            }
        }
        __syncthreads();

        #pragma unroll 4
        for (int dd = 0; dd < 32; dd++){
            const float4 w4 = *(const float4*)(Ws + dd*132 + 4*tx);
            const unsigned long long w0 = dup2(w4.x), w1 = dup2(w4.y),
                                     w2 = dup2(w4.z), w3 = dup2(w4.w);
            const float* er = Es + dd*102 + 2*ty;
            #pragma unroll
            for (int k = 0; k < 7; k++){
                const unsigned long long e2 = *(const unsigned long long*)(er + 16*k);
                ffma2(acc[k][0], e2, w0);
                ffma2(acc[k][1], e2, w1);
                ffma2(acc[k][2], e2, w2);
                ffma2(acc[k][3], e2, w3);
            }
        }
    }
    __syncthreads();

    float* base = g_scr + (size_t)bb * TBLK;
    float4 q1v = make_float4(0.f,0.f,0.f,0.f);
    if (m == 1) q1v = *(const float4*)(q1s + 4*tx);

    #pragma unroll
    for (int k = 0; k < 7; k++){
        const int n0 = 2*(ty + 8*k);
        if (n0 >= NN) continue;
        const int n1 = n0 + 1;
        float lo0,hi0,lo1,hi1,lo2,hi2,lo3,hi3;
        unpack2(acc[k][0], lo0, hi0);
        unpack2(acc[k][1], lo1, hi1);
        unpack2(acc[k][2], lo2, hi2);
        unpack2(acc[k][3], lo3, hi3);
        if (m == 0){
            float* K = base + OFF_K;
            K[(4*tx+0)*104 + n0] = lo0;  K[(4*tx+0)*104 + n1] = hi0;
            K[(4*tx+1)*104 + n0] = lo1;  K[(4*tx+1)*104 + n1] = hi1;
            K[(4*tx+2)*104 + n0] = lo2;  K[(4*tx+2)*104 + n1] = hi2;
            K[(4*tx+3)*104 + n0] = lo3;  K[(4*tx+3)*104 + n1] = hi3;
        } else if (m == 2){
            float* V = base + OFF_V;
            V[(4*tx+0)*108 + n0] = lo0;  V[(4*tx+0)*108 + n1] = hi0;
            V[(4*tx+1)*108 + n0] = lo1;  V[(4*tx+1)*108 + n1] = hi1;
            V[(4*tx+2)*108 + n0] = lo2;  V[(4*tx+2)*108 + n1] = hi2;
            V[(4*tx+3)*108 + n0] = lo3;  V[(4*tx+3)*108 + n1] = hi3;
        } else if (m == 3){
            float* P = base + OFF_P;
            *(float4*)(P + n0*132 + 4*tx) = make_float4(lo0,lo1,lo2,lo3);
            *(float4*)(P + n1*132 + 4*tx) = make_float4(hi0,hi1,hi2,hi3);
        } else {
            float* Q = base + OFF_Q;
            *(float4*)(Q + n0*132 + 4*tx) = make_float4(lo0+q1v.x, lo1+q1v.y, lo2+q1v.z, lo3+q1v.w);
            *(float4*)(Q + n1*132 + 4*tx) = make_float4(hi0+q1v.x, hi1+q1v.y, hi2+q1v.z, hi3+q1v.w);
        }
    }
}

// =====================================================================
// decode: 2 CTAs/SM. K+V in smem (110.5KB); P,Q streamed from L2.
// Phases: A' | C(128t -> mh) | DE(P from global, tanh, warp argmax) | final
// =====================================================================
__global__ __launch_bounds__(256, 2) void decode_kernel(Args a, int c0, float* __restrict__ out)
{
    if (!g_ok || g_psel < 0) return;
    extern __shared__ __align__(16) float sm[];
    float* Kt    = sm;                   // [128][104]  13312
    float* Vt    = sm + 13312;           // [128][108]  13824
    float* att   = sm + 27136;           // [8][112]    896
    float* mh    = att + 896;            // [128]
    float* maskv = mh + 128;             // [104]
    float* candv = maskv + 104;          // [8]
    int*   candi = (int*)(candv + 8);    // [8]
    int*   icur  = (int*)(candi + 8);

    const int bb = blockIdx.x;
    const int b  = c0 + bb;
    const int tid = threadIdx.x;
    const int lane = tid & 31, wid = tid >> 5;
    const int klen = g_klen;
    const int* pre = (const int*)a.p[g_psel];

    const float* __restrict__ scrP = g_scr + (size_t)bb * TBLK + OFF_P;
    const float* __restrict__ scrQ = g_scr + (size_t)bb * TBLK + OFF_Q;

    // bulk copy K,V into smem; prefetch P,Q into L2
    {
        const float4* src = (const float4*)(g_scr + (size_t)bb * TBLK);
        float4* dst = (float4*)sm;
        for (int i = tid; i < 27136/4; i += 256) dst[i] = src[i];
        for (int i = tid; i < 825; i += 256){
            const char* p = (const char*)scrP + (size_t)i * 128;   // covers P and Q (26400 fl)
            asm volatile("prefetch.global.L2 [%0];" :: "l"(p));
        }
    }
    if (tid < 104) maskv[tid] = 0.f;
    __syncthreads();
    if (tid < klen){
        int p = pre[b*klen + tid];
        p = (p >= 0 && p < NN) ? p : 0;
        maskv[p] = NEG_INF;
        out[b*NN + tid] = (float)p;
    }
    if (tid == 0){
        int last = pre[b*klen + (klen-1)];
        icur[0] = (last >= 0 && last < NN) ? last : 0;
    }
    __syncthreads();

    const int steps = NN - klen;
    for (int step = 0; step < steps; step++){
        const int cur = icur[0];

        // ---- Phase A: scores -> exp (no max-sub) -> Z -> normalized att ----
        {
            const int h = wid;
            const int nq = (lane < 25) ? lane : 24;
            const bool valid = (lane < 25);
            const float* qrow = scrQ + cur*132 + h*16;     // global (L2), broadcast
            const float4 q40 = *(const float4*)(qrow);
            const float4 q41 = *(const float4*)(qrow + 4);
            const float4 q42 = *(const float4*)(qrow + 8);
            const float4 q43 = *(const float4*)(qrow + 12);
            const float* kq = Kt + (h*16)*104 + 4*nq;
            unsigned long long a0 = 0ull, a1 = 0ull;
            float qv[16] = {q40.x,q40.y,q40.z,q40.w, q41.x,q41.y,q41.z,q41.w,
                            q42.x,q42.y,q42.z,q42.w, q43.x,q43.y,q43.z,q43.w};
            #pragma unroll
            for (int e = 0; e < 16; e++){
                const unsigned long long q2 = dup2(qv[e]);
                const ulonglong2 k2 = *(const ulonglong2*)(kq + e*104);
                ffma2(a0, q2, k2.x);
                ffma2(a1, q2, k2.y);
            }
            float s0,s1,s2,s3;
            unpack2(a0, s0, s1);
            unpack2(a1, s2, s3);
            const float4 m4 = *(const float4*)(maskv + 4*nq);
            float w0 = 0.f, w1 = 0.f, w2 = 0.f, w3 = 0.f;
            if (valid){
                w0 = expf(s0*0.25f + m4.x);   // expf(-inf)=0 masks visited
                w1 = expf(s1*0.25f + m4.y);
                w2 = expf(s2*0.25f + m4.z);
                w3 = expf(s3*0.25f + m4.w);
            }
            float zs = (w0+w1) + (w2+w3);
            #pragma unroll
            for (int o = 16; o; o >>= 1) zs += __shfl_xor_sync(0xffffffffu, zs, o);
            const float rz = 1.0f / zs;
            if (valid) *(float4*)(att + h*112 + 4*nq) = make_float4(w0*rz, w1*rz, w2*rz, w3*rz);
        }
        __syncthreads();

        // ---- Phase C: mh[c] = sum_n att_norm[h(c)][n]*V[c][n] (128 threads) ----
        if (tid < 128){
            const int c = tid;
            const float* ar = att + (c >> 4)*112;
            const float* vr = Vt + c*108;
            unsigned long long a0 = 0ull, a1 = 0ull;
            #pragma unroll 5
            for (int nq = 0; nq < 25; nq++){
                const ulonglong2 av = *(const ulonglong2*)(ar + 4*nq);
                const ulonglong2 vv = *(const ulonglong2*)(vr + 4*nq);
                ffma2(a0, av.x, vv.x);
                ffma2(a1, av.y, vv.y);
            }
            float s0,s1,s2,s3;
            unpack2(a0, s0, s1);
            unpack2(a1, s2, s3);
            mh[c] = (s0+s1) + (s2+s3);
        }
        __syncthreads();

        // ---- Phase DE: sc[n] = mh . P[n][:] (P from global), tanh, warp argmax ----
        if (tid < 128){
            const int n = tid;
            float v = NEG_INF;
            if (n < NN){
                const float* Prow = scrP + n*132;
                unsigned long long a0 = 0ull, a1 = 0ull;
                #pragma unroll 8
                for (int jq = 0; jq < 32; jq++){
                    const ulonglong2 mq = *(const ulonglong2*)(mh + 4*jq);
                    const ulonglong2 pq = *(const ulonglong2*)(Prow + 4*jq);
                    ffma2(a0, mq.x, pq.x);
                    ffma2(a1, mq.y, pq.y);
                }
                float s0,s1,s2,s3;
                unpack2(a0, s0, s1);
                unpack2(a1, s2, s3);
                const float sc = ((s0+s1) + (s2+s3)) * 0.08838834764831845f; // 1/sqrt(128)
                v = 10.f * tanhf(sc) + maskv[n];
            }
            float best = v; int bi = (n < NN) ? n : 127;
            #pragma unroll
            for (int o = 16; o; o >>= 1){
                const float ov = __shfl_down_sync(0xffffffffu, best, o);
                const int   oi = __shfl_down_sync(0xffffffffu, bi,   o);
                if (ov > best || (ov == best && oi < bi)){ best = ov; bi = oi; }
            }
            if (lane == 0){ candv[wid] = best; candi[wid] = bi; }
        }
        __syncthreads();

        // ---- final: reduce 4 candidates, update state ----
        if (tid == 0){
            float best = candv[0]; int bi = candi[0];
            #pragma unroll
            for (int w = 1; w < 4; w++){
                const float ov = candv[w]; const int oi = candi[w];
                if (ov > best || (ov == best && oi < bi)){ best = ov; bi = oi; }
            }
            maskv[bi] = NEG_INF;
            icur[0] = bi;
            out[b*NN + klen + step] = (float)bi;
        }
        __syncthreads();
    }
}

// =====================================================================
extern "C" void kernel_launch(void* const* d_in, const int* in_sizes, int n_in,
                              void* d_out, int out_size)
{
    Args a;
    for (int i = 0; i < 10; i++){
        a.p[i]  = (i < n_in) ? d_in[i] : d_in[0];
        a.sz[i] = (i < n_in) ? (long)in_sizes[i] : 0;
    }
    a.n = (n_in < 10) ? n_in : 10;
    a.batch = out_size / NN;
    if (a.batch < 1) a.batch = 1;
    float* out = (float*)d_out;

    prep_kernel<<<1, 32>>>(a);
    prefill_kernel<<<a.batch, 128>>>(a, out);

    const int smem_bytes = (13312 + 13824 + 896 + 128 + 104 + 8 + 8 + 4) * 4;   // 113136B
    (void)cudaFuncSetAttribute(decode_kernel, cudaFuncAttributeMaxDynamicSharedMemorySize, smem_bytes);

    for (int c0 = 0; c0 < a.batch; c0 += CH){
        const int cb = (a.batch - c0 < CH) ? (a.batch - c0) : CH;
        dim3 g(cb, 4);
        gemm_kernel<<<g, 256>>>(a, c0);
        decode_kernel<<<cb, 256, smem_bytes>>>(a, c0, out);
    }
}

// round 14
// speedup vs baseline: 1.0360x; 1.0360x over previous
#include <cuda_runtime.h>
#include <cstdint>

#define NN 100
#define DD 128
#define CH 2048
#define NEG_INF __int_as_float(0xff800000)

// scratch/decode tables, ALL n-major [100][132] floats:
#define OFF_K 0
#define OFF_V 13200
#define OFF_P 26400
#define OFF_Q 39600
#define TBLK  52800

struct Args { const void* p[10]; long sz[10]; int n; int batch; };

__device__ float g_scr[(size_t)CH * TBLK];   // ~432MB, zero-init
__device__ int g_psel, g_klen, g_ok, g_enc, g_widx[5];

// ---------------- f32x2 helpers ----------------
__device__ __forceinline__ void ffma2(unsigned long long &d, unsigned long long a, unsigned long long b){
    asm("fma.rn.f32x2 %0, %1, %2, %0;" : "+l"(d) : "l"(a), "l"(b));
}
__device__ __forceinline__ unsigned long long dup2(float x){
    unsigned long long r; asm("mov.b64 %0, {%1, %1};" : "=l"(r) : "f"(x)); return r;
}
__device__ __forceinline__ void unpack2(unsigned long long v, float &lo, float &hi){
    asm("mov.b64 {%0, %1}, %2;" : "=f"(lo), "=f"(hi) : "l"(v));
}

// =====================================================================
// prep: device-side role detection by content. (proven)
// =====================================================================
__global__ void prep_kernel(Args a)
{
    if (threadIdx.x != 0) return;
    int ok = 1;

    int encIdx = 0; long mxs = -1;
    for (int i = 0; i < a.n; i++) if (a.sz[i] > mxs){ mxs = a.sz[i]; encIdx = i; }
    const long want = (long)a.batch * NN * DD;
    long scale = 1;
    if      (mxs == want)     scale = 1;
    else if (mxs == want * 4) scale = 4;
    else ok = 0;

    int psel = -1;
    for (int i = 0; i < a.n; i++){
        if (a.sz[i] / scale < 64) continue;
        const int* q = (const int*)a.p[i];
        bool good = true; int mn = 1 << 30, mxv = -1;
        for (int k = 0; k < 64; k++){
            const int v = q[k];
            if (v < 0 || v >= NN){ good = false; break; }
            mn = v < mn ? v : mn; mxv = v > mxv ? v : mxv;
        }
        if (good && mxv > mn){ psel = i; break; }
    }
    int klen = 10;
    if (psel >= 0 && a.batch > 0){
        const long kl = (a.sz[psel] / scale) / a.batch;
        if (kl >= 1 && kl <= NN) klen = (int)kl; else ok = 0;
    } else ok = 0;

    int prob = -1;
    for (int i = 0; i < a.n; i++){
        if (i == encIdx || i == psel) continue;
        if (a.sz[i] / scale == (long)DD * DD) continue;
        const float* f = (const float*)a.p[i];
        bool good = true;
        for (int k = 0; k < 64; k++){
            const float v = f[k];
            if (!(v > 0.f && v < 1.f)){ good = false; break; }
        }
        if (good){ prob = i; break; }
    }

    int w[10]; int nw = 0;
    for (int i = 0; i < a.n; i++)
        if (a.sz[i] / scale == (long)DD * DD && nw < 10) w[nw++] = i;
    if (nw != 5){ ok = 0; w[0]=2; w[1]=3; w[2]=4; w[3]=5; w[4]=6; }

    const bool dict = (prob < 0) ? true : (prob < encIdx);
    // roles: 0=Wq_first 1=Wq_last 2=Wk 3=Wv 4=Wcomb
    if (dict){ g_widx[0]=w[0]; g_widx[1]=w[1]; g_widx[2]=w[2]; g_widx[3]=w[3]; g_widx[4]=w[4]; }
    else     { g_widx[0]=w[2]; g_widx[1]=w[3]; g_widx[2]=w[1]; g_widx[3]=w[4]; g_widx[4]=w[0]; }

    g_psel = psel; g_klen = klen; g_enc = encIdx; g_ok = ok;
}

__global__ void prefill_kernel(Args a, float* __restrict__ out)
{
    const int b = blockIdx.x, tid = threadIdx.x;
    for (int j = tid; j < NN; j += blockDim.x) out[b*NN + j] = 1.0f;
    const int psel = g_psel, klen = g_klen;
    if (psel >= 0 && tid < klen){
        const int* pre = (const int*)a.p[psel];
        int p = pre[b*klen + tid];
        out[b*NN + tid] = (float)((p >= 0 && p < NN) ? p : 0);
    }
}

// =====================================================================
// gemm: grid (chunk, 4); 256 threads; f32x2 core; ALL outputs n-major.
//  m=0: K   m=1: Q(+q1)   m=2: V   m=3: P = E@Wcomb^T
// =====================================================================
__global__ __launch_bounds__(256, 2) void gemm_kernel(Args a, int c0)
{
    if (!g_ok) return;
    __shared__ __align__(16) float Es[32*102 + 16];
    __shared__ __align__(16) float Ws[32*132];
    __shared__ __align__(16) float q1s[128];

    const int bb = blockIdx.x, m = blockIdx.y;
    const int b = c0 + bb;
    const int tid = threadIdx.x;
    const int tx = tid & 31;
    const int ty = tid >> 5;

    const int role = (m==0) ? 2 : (m==1) ? 1 : (m==2) ? 3 : 4;
    const float* W   = (const float*)a.p[g_widx[role]];
    const float* enc = (const float*)a.p[g_enc];
    const float* Eb  = enc + (size_t)b * (NN*DD);
    const int klen = g_klen;

    if (m == 1 && tid < 128){
        const int* pre = (const int*)a.p[g_psel];
        int last = pre[b*klen + (klen-1)];
        last = (last >= 0 && last < NN) ? last : 0;
        const float* er = Eb + last*DD;
        const float* Wqf = (const float*)a.p[g_widx[0]];
        float s = 0.f;
        for (int d = 0; d < DD; d++) s += er[d] * Wqf[d*DD + tid];
        q1s[tid] = s;
    }

    unsigned long long acc[7][4];
    #pragma unroll
    for (int k = 0; k < 7; k++){ acc[k][0]=0ull; acc[k][1]=0ull; acc[k][2]=0ull; acc[k][3]=0ull; }

    for (int dch = 0; dch < 4; dch++){
        const int d0 = dch * 32;
        __syncthreads();
        for (int e = tid; e < 3200; e += 256){
            const int n = e >> 5, dd = e & 31;
            Es[dd*102 + n] = Eb[n*DD + d0 + dd];
        }
        if (m < 3){
            for (int e = tid; e < 4096; e += 256){
                const int dd = e >> 7, c = e & 127;
                Ws[dd*132 + c] = W[(d0+dd)*DD + c];
            }
        } else {
            for (int e = tid; e < 4096; e += 256){
                const int c = e >> 5, dd = e & 31;
                Ws[dd*132 + c] = W[c*DD + d0 + dd];
            }
        }
        __syncthreads();

        #pragma unroll 4
        for (int dd = 0; dd < 32; dd++){
            const float4 w4 = *(const float4*)(Ws + dd*132 + 4*tx);
            const unsigned long long w0 = dup2(w4.x), w1 = dup2(w4.y),
                                     w2 = dup2(w4.z), w3 = dup2(w4.w);
            const float* er = Es + dd*102 + 2*ty;
            #pragma unroll
            for (int k = 0; k < 7; k++){
                const unsigned long long e2 = *(const unsigned long long*)(er + 16*k);
                ffma2(acc[k][0], e2, w0);
                ffma2(acc[k][1], e2, w1);
                ffma2(acc[k][2], e2, w2);
                ffma2(acc[k][3], e2, w3);
            }
        }
    }
    __syncthreads();

    float* dst = g_scr + (size_t)bb * TBLK
               + ((m==0) ? OFF_K : (m==1) ? OFF_Q : (m==2) ? OFF_V : OFF_P);
    float4 q1v = make_float4(0.f,0.f,0.f,0.f);
    if (m == 1) q1v = *(const float4*)(q1s + 4*tx);

    #pragma unroll
    for (int k = 0; k < 7; k++){
        const int n0 = 2*(ty + 8*k);
        if (n0 >= NN) continue;
        const int n1 = n0 + 1;
        float lo0,hi0,lo1,hi1,lo2,hi2,lo3,hi3;
        unpack2(acc[k][0], lo0, hi0);
        unpack2(acc[k][1], lo1, hi1);
        unpack2(acc[k][2], lo2, hi2);
        unpack2(acc[k][3], lo3, hi3);
        *(float4*)(dst + n0*132 + 4*tx) = make_float4(lo0+q1v.x, lo1+q1v.y, lo2+q1v.z, lo3+q1v.w);
        *(float4*)(dst + n1*132 + 4*tx) = make_float4(hi0+q1v.x, hi1+q1v.y, hi2+q1v.z, hi3+q1v.w);
    }
}

// =====================================================================
// decode: unvisited-set compaction. Tables n-major in smem (~206KB).
// Phases: A (head,node) pairs -> exp weights | C rows+Z-fold -> mh |
//         DE act-node dots (no tanh: monotone) + argmax | final swap-remove.
// =====================================================================
__global__ __launch_bounds__(256, 1) void decode_kernel(Args a, int c0, float* __restrict__ out)
{
    if (!g_ok || g_psel < 0) return;
    extern __shared__ __align__(16) float sm[];
    float* Kt   = sm + OFF_K;            // [100][132]
    float* Vt   = sm + OFF_V;
    float* Pt   = sm + OFF_P;
    float* Qt   = sm + OFF_Q;
    float* att  = sm + TBLK;             // [8][100] unnormalized weights
    float* mh   = att + 800;             // [128]
    float* candv= mh + 128;              // [4]
    int* candn  = (int*)(candv + 4);     // [4] node
    int* candj  = candn + 4;             // [4] position
    int* idxs   = candj + 4;             // [100] active node list (16B aligned)
    int* icur   = idxs + 100;
    int* visd   = icur + 4;              // [100]

    const int bb = blockIdx.x;
    const int b  = c0 + bb;
    const int tid = threadIdx.x;
    const int lane = tid & 31, wid = tid >> 5;
    const int klen = g_klen;
    const int* pre = (const int*)a.p[g_psel];

    {
        const float4* src = (const float4*)(g_scr + (size_t)bb * TBLK);
        float4* dst = (float4*)sm;
        for (int i = tid; i < TBLK/4; i += 256) dst[i] = src[i];
    }
    if (tid < NN) visd[tid] = 0;
    __syncthreads();
    if (tid < klen){
        int p = pre[b*klen + tid];
        p = (p >= 0 && p < NN) ? p : 0;
        visd[p] = 1;
        out[b*NN + tid] = (float)p;
    }
    __syncthreads();
    if (tid == 0){
        int m = 0;
        for (int n = 0; n < NN; n++) if (!visd[n]) idxs[m++] = n;
        int last = pre[b*klen + (klen-1)];
        icur[0] = (last >= 0 && last < NN) ? last : 0;
    }
    __syncthreads();

    const int steps = NN - klen;
    for (int step = 0; step < steps; step++){
        const int act = steps - step;         // current active count
        const int cur = icur[0];

        // ---- Phase A: w[h][j] = exp(q_h . K[idx[j]]_h / 4), FULL 16-elem dot ----
        for (int p = tid; p < 8*act; p += 256){
            const int j = p >> 3, h = p & 7;
            const float* Krow = Kt + idxs[j]*132 + h*16;
            const float* Qrow = Qt + cur*132 + h*16;
            const ulonglong2 k0 = *(const ulonglong2*)(Krow);
            const ulonglong2 k1 = *(const ulonglong2*)(Krow + 4);
            const ulonglong2 k2 = *(const ulonglong2*)(Krow + 8);
            const ulonglong2 k3 = *(const ulonglong2*)(Krow + 12);
            const ulonglong2 q0 = *(const ulonglong2*)(Qrow);
            const ulonglong2 q1 = *(const ulonglong2*)(Qrow + 4);
            const ulonglong2 q2 = *(const ulonglong2*)(Qrow + 8);
            const ulonglong2 q3 = *(const ulonglong2*)(Qrow + 12);
            unsigned long long a0 = 0ull, a1 = 0ull;
            ffma2(a0, k0.x, q0.x); ffma2(a1, k0.y, q0.y);
            ffma2(a0, k1.x, q1.x); ffma2(a1, k1.y, q1.y);
            ffma2(a0, k2.x, q2.x); ffma2(a1, k2.y, q2.y);
            ffma2(a0, k3.x, q3.x); ffma2(a1, k3.y, q3.y);
            float s0,s1,s2,s3;
            unpack2(a0, s0, s1);
            unpack2(a1, s2, s3);
            att[h*100 + j] = expf(((s0+s1) + (s2+s3)) * 0.25f);
        }
        __syncthreads();

        // ---- Phase C: mh[c] = (sum_j w[h][j]*V[idx[j]][c]) / (sum_j w[h][j]) ----
        if (tid < 128){
            const int c = tid;
            const float* ar = att + (c >> 4)*100;
            float accv = 0.f, accz = 0.f;
            int jj = 0;
            for (; jj + 4 <= act; jj += 4){
                const int4   i4 = *(const int4*)(idxs + jj);
                const float4 a4 = *(const float4*)(ar + jj);
                accv += a4.x * Vt[i4.x*132 + c];  accz += a4.x;
                accv += a4.y * Vt[i4.y*132 + c];  accz += a4.y;
                accv += a4.z * Vt[i4.z*132 + c];  accz += a4.z;
                accv += a4.w * Vt[i4.w*132 + c];  accz += a4.w;
            }
            for (; jj < act; jj++){
                const float av = ar[jj];
                accv += av * Vt[idxs[jj]*132 + c];
                accz += av;
            }
            mh[c] = accv / accz;
        }
        __syncthreads();

        // ---- Phase DE: sc = mh . P[node] for active nodes; argmax (node tie-break) ----
        if (tid < 128){
            const int j = tid;
            float v = NEG_INF; int node = NN + tid;
            if (j < act){
                node = idxs[j];
                const float* Prow = Pt + node*132;
                unsigned long long a0 = 0ull, a1 = 0ull;
                #pragma unroll 8
                for (int jq = 0; jq < 32; jq++){
                    const ulonglong2 mq = *(const ulonglong2*)(mh + 4*jq);
                    const ulonglong2 pq = *(const ulonglong2*)(Prow + 4*jq);
                    ffma2(a0, mq.x, pq.x);
                    ffma2(a1, mq.y, pq.y);
                }
                float s0,s1,s2,s3;
                unpack2(a0, s0, s1);
                unpack2(a1, s2, s3);
                v = (s0+s1) + (s2+s3);     // tanh & 1/sqrt(d) are monotone: skip
            }
            float best = v; int bn = node, bj = j;
            #pragma unroll
            for (int o = 16; o; o >>= 1){
                const float ov = __shfl_down_sync(0xffffffffu, best, o);
                const int   on = __shfl_down_sync(0xffffffffu, bn,   o);
                const int   oj = __shfl_down_sync(0xffffffffu, bj,   o);
                if (ov > best || (ov == best && on < bn)){ best = ov; bn = on; bj = oj; }
            }
            if (lane == 0){ candv[wid] = best; candn[wid] = bn; candj[wid] = bj; }
        }
        __syncthreads();

        // ---- final: pick winner, swap-remove from active list ----
        if (tid == 0){
            float best = candv[0]; int bn = candn[0], bj = candj[0];
            #pragma unroll
            for (int w = 1; w < 4; w++){
                const float ov = candv[w];
                const int on = candn[w], oj = candj[w];
                if (ov > best || (ov == best && on < bn)){ best = ov; bn = on; bj = oj; }
            }
            idxs[bj] = idxs[act-1];
            icur[0] = bn;
            out[b*NN + klen + step] = (float)bn;
        }
        __syncthreads();
    }
}

// =====================================================================
extern "C" void kernel_launch(void* const* d_in, const int* in_sizes, int n_in,
                              void* d_out, int out_size)
{
    Args a;
    for (int i = 0; i < 10; i++){
        a.p[i]  = (i < n_in) ? d_in[i] : d_in[0];
        a.sz[i] = (i < n_in) ? (long)in_sizes[i] : 0;
    }
    a.n = (n_in < 10) ? n_in : 10;
    a.batch = out_size / NN;
    if (a.batch < 1) a.batch = 1;
    float* out = (float*)d_out;

    prep_kernel<<<1, 32>>>(a);
    prefill_kernel<<<a.batch, 128>>>(a, out);

    const int smem_floats = TBLK + 800 + 128 + 4 + 4 + 4 + 100 + 4 + 100;
    const int smem_bytes = smem_floats * 4;    // ~215.8KB
    (void)cudaFuncSetAttribute(decode_kernel, cudaFuncAttributeMaxDynamicSharedMemorySize, smem_bytes);

    for (int c0 = 0; c0 < a.batch; c0 += CH){
        const int cb = (a.batch - c0 < CH) ? (a.batch - c0) : CH;
        dim3 g(cb, 4);
        gemm_kernel<<<g, 256>>>(a, c0);
        decode_kernel<<<cb, 256, smem_bytes>>>(a, c0, out);
    }
}

// round 15
// speedup vs baseline: 1.0444x; 1.0081x over previous
#include <cuda_runtime.h>
#include <cstdint>

#define NN 100
#define DD 128
#define CH 2048
#define NEG_INF __int_as_float(0xff800000)

// scratch per batch, n-major [100][132]: K@0 V@13200 P@26400 Q@39600
#define OFF_K 0
#define OFF_V 13200
#define OFF_P 26400
#define OFF_Q 39600
#define TBLK  52800

struct Args { const void* p[10]; long sz[10]; int n; int batch; };

__device__ float g_scr[(size_t)CH * TBLK];   // ~432MB, zero-init
__device__ int g_psel, g_klen, g_ok, g_enc, g_widx[5];

// ---------------- f32x2 helpers ----------------
__device__ __forceinline__ void ffma2(unsigned long long &d, unsigned long long a, unsigned long long b){
    asm("fma.rn.f32x2 %0, %1, %2, %0;" : "+l"(d) : "l"(a), "l"(b));
}
__device__ __forceinline__ unsigned long long dup2(float x){
    unsigned long long r; asm("mov.b64 %0, {%1, %1};" : "=l"(r) : "f"(x)); return r;
}
__device__ __forceinline__ void unpack2(unsigned long long v, float &lo, float &hi){
    asm("mov.b64 {%0, %1}, %2;" : "=f"(lo), "=f"(hi) : "l"(v));
}

// =====================================================================
// prep: device-side role detection by content. (proven)
// =====================================================================
__global__ void prep_kernel(Args a)
{
    if (threadIdx.x != 0) return;
    int ok = 1;

    int encIdx = 0; long mxs = -1;
    for (int i = 0; i < a.n; i++) if (a.sz[i] > mxs){ mxs = a.sz[i]; encIdx = i; }
    const long want = (long)a.batch * NN * DD;
    long scale = 1;
    if      (mxs == want)     scale = 1;
    else if (mxs == want * 4) scale = 4;
    else ok = 0;

    int psel = -1;
    for (int i = 0; i < a.n; i++){
        if (a.sz[i] / scale < 64) continue;
        const int* q = (const int*)a.p[i];
        bool good = true; int mn = 1 << 30, mxv = -1;
        for (int k = 0; k < 64; k++){
            const int v = q[k];
            if (v < 0 || v >= NN){ good = false; break; }
            mn = v < mn ? v : mn; mxv = v > mxv ? v : mxv;
        }
        if (good && mxv > mn){ psel = i; break; }
    }
    int klen = 10;
    if (psel >= 0 && a.batch > 0){
        const long kl = (a.sz[psel] / scale) / a.batch;
        if (kl >= 1 && kl <= NN) klen = (int)kl; else ok = 0;
    } else ok = 0;

    int prob = -1;
    for (int i = 0; i < a.n; i++){
        if (i == encIdx || i == psel) continue;
        if (a.sz[i] / scale == (long)DD * DD) continue;
        const float* f = (const float*)a.p[i];
        bool good = true;
        for (int k = 0; k < 64; k++){
            const float v = f[k];
            if (!(v > 0.f && v < 1.f)){ good = false; break; }
        }
        if (good){ prob = i; break; }
    }

    int w[10]; int nw = 0;
    for (int i = 0; i < a.n; i++)
        if (a.sz[i] / scale == (long)DD * DD && nw < 10) w[nw++] = i;
    if (nw != 5){ ok = 0; w[0]=2; w[1]=3; w[2]=4; w[3]=5; w[4]=6; }

    const bool dict = (prob < 0) ? true : (prob < encIdx);
    // roles: 0=Wq_first 1=Wq_last 2=Wk 3=Wv 4=Wcomb
    if (dict){ g_widx[0]=w[0]; g_widx[1]=w[1]; g_widx[2]=w[2]; g_widx[3]=w[3]; g_widx[4]=w[4]; }
    else     { g_widx[0]=w[2]; g_widx[1]=w[3]; g_widx[2]=w[1]; g_widx[3]=w[4]; g_widx[4]=w[0]; }

    g_psel = psel; g_klen = klen; g_enc = encIdx; g_ok = ok;
}

__global__ void prefill_kernel(Args a, float* __restrict__ out)
{
    const int b = blockIdx.x, tid = threadIdx.x;
    for (int j = tid; j < NN; j += blockDim.x) out[b*NN + j] = 1.0f;
    const int psel = g_psel, klen = g_klen;
    if (psel >= 0 && tid < klen){
        const int* pre = (const int*)a.p[psel];
        int p = pre[b*klen + tid];
        out[b*NN + tid] = (float)((p >= 0 && p < NN) ? p : 0);
    }
}

// =====================================================================
// gemm: grid (chunk, 4); 256 threads; f32x2 core; ALL outputs n-major. (proven)
// =====================================================================
__global__ __launch_bounds__(256, 2) void gemm_kernel(Args a, int c0)
{
    if (!g_ok) return;
    __shared__ __align__(16) float Es[32*102 + 16];
    __shared__ __align__(16) float Ws[32*132];
    __shared__ __align__(16) float q1s[128];

    const int bb = blockIdx.x, m = blockIdx.y;
    const int b = c0 + bb;
    const int tid = threadIdx.x;
    const int tx = tid & 31;
    const int ty = tid >> 5;

    const int role = (m==0) ? 2 : (m==1) ? 1 : (m==2) ? 3 : 4;
    const float* W   = (const float*)a.p[g_widx[role]];
    const float* enc = (const float*)a.p[g_enc];
    const float* Eb  = enc + (size_t)b * (NN*DD);
    const int klen = g_klen;

    if (m == 1 && tid < 128){
        const int* pre = (const int*)a.p[g_psel];
        int last = pre[b*klen + (klen-1)];
        last = (last >= 0 && last < NN) ? last : 0;
        const float* er = Eb + last*DD;
        const float* Wqf = (const float*)a.p[g_widx[0]];
        float s = 0.f;
        for (int d = 0; d < DD; d++) s += er[d] * Wqf[d*DD + tid];
        q1s[tid] = s;
    }

    unsigned long long acc[7][4];
    #pragma unroll
    for (int k = 0; k < 7; k++){ acc[k][0]=0ull; acc[k][1]=0ull; acc[k][2]=0ull; acc[k][3]=0ull; }

    for (int dch = 0; dch < 4; dch++){
        const int d0 = dch * 32;
        __syncthreads();
        for (int e = tid; e < 3200; e += 256){
            const int n = e >> 5, dd = e & 31;
            Es[dd*102 + n] = Eb[n*DD + d0 + dd];
        }
        if (m < 3){
            for (int e = tid; e < 4096; e += 256){
                const int dd = e >> 7, c = e & 127;
                Ws[dd*132 + c] = W[(d0+dd)*DD + c];
            }
        } else {
            for (int e = tid; e < 4096; e += 256){
                const int c = e >> 5, dd = e & 31;
                Ws[dd*132 + c] = W[c*DD + d0 + dd];
            }
        }
        __syncthreads();

        #pragma unroll 4
        for (int dd = 0; dd < 32; dd++){
            const float4 w4 = *(const float4*)(Ws + dd*132 + 4*tx);
            const unsigned long long w0 = dup2(w4.x), w1 = dup2(w4.y),
                                     w2 = dup2(w4.z), w3 = dup2(w4.w);
            const float* er = Es + dd*102 + 2*ty;
            #pragma unroll
            for (int k = 0; k < 7; k++){
                const unsigned long long e2 = *(const unsigned long long*)(er + 16*k);
                ffma2(acc[k][0], e2, w0);
                ffma2(acc[k][1], e2, w1);
                ffma2(acc[k][2], e2, w2);
                ffma2(acc[k][3], e2, w3);
            }
        }
    }
    __syncthreads();

    float* dst = g_scr + (size_t)bb * TBLK
               + ((m==0) ? OFF_K : (m==1) ? OFF_Q : (m==2) ? OFF_V : OFF_P);
    float4 q1v = make_float4(0.f,0.f,0.f,0.f);
    if (m == 1) q1v = *(const float4*)(q1s + 4*tx);

    #pragma unroll
    for (int k = 0; k < 7; k++){
        const int n0 = 2*(ty + 8*k);
        if (n0 >= NN) continue;
        const int n1 = n0 + 1;
        float lo0,hi0,lo1,hi1,lo2,hi2,lo3,hi3;
        unpack2(acc[k][0], lo0, hi0);
        unpack2(acc[k][1], lo1, hi1);
        unpack2(acc[k][2], lo2, hi2);
        unpack2(acc[k][3], lo3, hi3);
        *(float4*)(dst + n0*132 + 4*tx) = make_float4(lo0+q1v.x, lo1+q1v.y, lo2+q1v.z, lo3+q1v.w);
        *(float4*)(dst + n1*132 + 4*tx) = make_float4(hi0+q1v.x, hi1+q1v.y, hi2+q1v.z, hi3+q1v.w);
    }
}

// =====================================================================
// decode2: TWO batch elements per CTA, phases interleaved (bsel = tid>>7).
// K+V in smem (211KB for both); P,Q streamed from L2. 4 barriers / 2 steps.
// =====================================================================
__global__ __launch_bounds__(256, 1) void decode_kernel(Args a, int c0, int cb, float* __restrict__ out)
{
    if (!g_ok || g_psel < 0) return;
    extern __shared__ __align__(16) float sm[];
    float* smKV  = sm;                    // [2][26400]: K@+0, V@+13200
    float* att   = sm + 52800;            // [2][800]
    float* mh    = att + 1600;            // [2][128]
    float* candv = mh + 256;              // [8]  (4 per batch)
    int* candn   = (int*)(candv + 8);     // [8]
    int* candj   = candn + 8;             // [8]
    int* idxs2   = candj + 8;             // [2][100] (16B aligned)
    int* icur2   = idxs2 + 200;           // [2]
    int* visd    = icur2 + 2;             // [2][100]

    const int bb  = blockIdx.x;
    const int tid = threadIdx.x;
    const int lane = tid & 31, wid = tid >> 5;
    const int klen = g_klen;
    const int* pre = (const int*)a.p[g_psel];

    const int bl0 = 2*bb;                          // local (chunk) batch indices
    const int bl1 = (2*bb+1 < cb) ? (2*bb+1) : bl0;
    const int bg0 = c0 + bl0, bg1 = c0 + bl1;      // global batch indices

    const float* scrP0 = g_scr + (size_t)bl0 * TBLK + OFF_P;
    const float* scrP1 = g_scr + (size_t)bl1 * TBLK + OFF_P;
    const float* scrQ0 = g_scr + (size_t)bl0 * TBLK + OFF_Q;
    const float* scrQ1 = g_scr + (size_t)bl1 * TBLK + OFF_Q;

    // load K+V for both batches (contiguous 26400 floats each in scratch)
    {
        const float4* s0 = (const float4*)(g_scr + (size_t)bl0 * TBLK);
        const float4* s1 = (const float4*)(g_scr + (size_t)bl1 * TBLK);
        float4* d0 = (float4*)(smKV);
        float4* d1 = (float4*)(smKV + 26400);
        for (int i = tid; i < 6600; i += 256){ d0[i] = s0[i]; d1[i] = s1[i]; }
        // prefetch P+Q (26400 floats = 825 x 128B per batch) into L2
        for (int i = tid; i < 825; i += 256){
            asm volatile("prefetch.global.L2 [%0];" :: "l"((const char*)scrP0 + (size_t)i*128));
            asm volatile("prefetch.global.L2 [%0];" :: "l"((const char*)scrP1 + (size_t)i*128));
        }
    }
    if (tid < 200) visd[tid] = 0;
    __syncthreads();
    if (tid < 2*klen){
        const int bsel = (tid >= klen) ? 1 : 0;
        const int k = tid - bsel*klen;
        const int bg = bsel ? bg1 : bg0;
        int p = pre[bg*klen + k];
        p = (p >= 0 && p < NN) ? p : 0;
        visd[bsel*100 + p] = 1;
        out[bg*NN + k] = (float)p;
    }
    __syncthreads();
    if (tid < 2){
        int* idl = idxs2 + tid*100;
        const int* vd = visd + tid*100;
        int m = 0;
        for (int n = 0; n < NN; n++) if (!vd[n]) idl[m++] = n;
        const int bg = tid ? bg1 : bg0;
        int last = pre[bg*klen + (klen-1)];
        icur2[tid] = (last >= 0 && last < NN) ? last : 0;
    }
    __syncthreads();

    const int steps = NN - klen;
    for (int step = 0; step < steps; step++){
        const int act = steps - step;

        // ---- Phase A (both batches): att[b][h][j] = exp(q.K/4) ----
        {
            const int tot = 16*act;
            for (int p = tid; p < tot; p += 256){
                const int bsel = (p >= 8*act) ? 1 : 0;
                const int pp = p - 8*act*bsel;
                const int j = pp >> 3, h = pp & 7;
                const float* Krow = smKV + bsel*26400 + idxs2[bsel*100 + j]*132 + h*16;
                const float* Qrow = (bsel ? scrQ1 : scrQ0) + icur2[bsel]*132 + h*16;
                const ulonglong2 k0 = *(const ulonglong2*)(Krow);
                const ulonglong2 k1 = *(const ulonglong2*)(Krow + 4);
                const ulonglong2 k2 = *(const ulonglong2*)(Krow + 8);
                const ulonglong2 k3 = *(const ulonglong2*)(Krow + 12);
                const ulonglong2 q0 = *(const ulonglong2*)(Qrow);
                const ulonglong2 q1 = *(const ulonglong2*)(Qrow + 4);
                const ulonglong2 q2 = *(const ulonglong2*)(Qrow + 8);
                const ulonglong2 q3 = *(const ulonglong2*)(Qrow + 12);
                unsigned long long a0 = 0ull, a1 = 0ull;
                ffma2(a0, k0.x, q0.x); ffma2(a1, k0.y, q0.y);
                ffma2(a0, k1.x, q1.x); ffma2(a1, k1.y, q1.y);
                ffma2(a0, k2.x, q2.x); ffma2(a1, k2.y, q2.y);
                ffma2(a0, k3.x, q3.x); ffma2(a1, k3.y, q3.y);
                float s0,s1,s2,s3;
                unpack2(a0, s0, s1);
                unpack2(a1, s2, s3);
                att[bsel*800 + h*100 + j] = expf(((s0+s1) + (s2+s3)) * 0.25f);
            }
        }
        __syncthreads();

        // ---- Phase C (both): mh[b][c] = (sum_j w*V[idx[j]][c]) / (sum_j w) ----
        {
            const int c = tid & 127, bsel = tid >> 7;
            const float* ar = att + bsel*800 + (c >> 4)*100;
            const float* Vb = smKV + bsel*26400 + 13200;
            const int* idl = idxs2 + bsel*100;
            float accv = 0.f, accz = 0.f;
            int jj = 0;
            for (; jj + 4 <= act; jj += 4){
                const int4   i4 = *(const int4*)(idl + jj);
                const float4 a4 = *(const float4*)(ar + jj);
                accv += a4.x * Vb[i4.x*132 + c];  accz += a4.x;
                accv += a4.y * Vb[i4.y*132 + c];  accz += a4.y;
                accv += a4.z * Vb[i4.z*132 + c];  accz += a4.z;
                accv += a4.w * Vb[i4.w*132 + c];  accz += a4.w;
            }
            for (; jj < act; jj++){
                const float av = ar[jj];
                accv += av * Vb[idl[jj]*132 + c];
                accz += av;
            }
            mh[bsel*128 + c] = accv / accz;
        }
        __syncthreads();

        // ---- Phase DE (both): sc = mh.P[node] from L2; warp argmax ----
        {
            const int bsel = tid >> 7, j = tid & 127;
            const int* idl = idxs2 + bsel*100;
            float v = NEG_INF; int node = NN + j, bj = j;
            if (j < act){
                node = idl[j];
                const float* Prow = (bsel ? scrP1 : scrP0) + node*132;
                const float* mhb = mh + bsel*128;
                unsigned long long a0 = 0ull, a1 = 0ull;
                #pragma unroll 8
                for (int jq = 0; jq < 32; jq++){
                    const ulonglong2 mq = *(const ulonglong2*)(mhb + 4*jq);
                    const ulonglong2 pq = *(const ulonglong2*)(Prow + 4*jq);
                    ffma2(a0, mq.x, pq.x);
                    ffma2(a1, mq.y, pq.y);
                }
                float s0,s1,s2,s3;
                unpack2(a0, s0, s1);
                unpack2(a1, s2, s3);
                v = (s0+s1) + (s2+s3);     // tanh & 1/sqrt(d) monotone: skip
            }
            float best = v; int bn = node;
            #pragma unroll
            for (int o = 16; o; o >>= 1){
                const float ov = __shfl_down_sync(0xffffffffu, best, o);
                const int   on = __shfl_down_sync(0xffffffffu, bn,   o);
                const int   oj = __shfl_down_sync(0xffffffffu, bj,   o);
                if (ov > best || (ov == best && on < bn)){ best = ov; bn = on; bj = oj; }
            }
            if (lane == 0){
                const int slot = bsel*4 + (wid & 3);
                candv[slot] = best; candn[slot] = bn; candj[slot] = bj;
            }
        }
        __syncthreads();

        // ---- final (2 threads): reduce, swap-remove, emit ----
        if (tid < 2){
            const int base = tid*4;
            float best = candv[base]; int bn = candn[base], bj = candj[base];
            #pragma unroll
            for (int w = 1; w < 4; w++){
                const float ov = candv[base+w];
                const int on = candn[base+w], oj = candj[base+w];
                if (ov > best || (ov == best && on < bn)){ best = ov; bn = on; bj = oj; }
            }
            int* idl = idxs2 + tid*100;
            idl[bj] = idl[act-1];
            icur2[tid] = bn;
            const int bg = tid ? bg1 : bg0;
            out[bg*NN + klen + step] = (float)bn;
        }
        __syncthreads();
    }
}

// =====================================================================
extern "C" void kernel_launch(void* const* d_in, const int* in_sizes, int n_in,
                              void* d_out, int out_size)
{
    Args a;
    for (int i = 0; i < 10; i++){
        a.p[i]  = (i < n_in) ? d_in[i] : d_in[0];
        a.sz[i] = (i < n_in) ? (long)in_sizes[i] : 0;
    }
    a.n = (n_in < 10) ? n_in : 10;
    a.batch = out_size / NN;
    if (a.batch < 1) a.batch = 1;
    float* out = (float*)d_out;

    prep_kernel<<<1, 32>>>(a);
    prefill_kernel<<<a.batch, 128>>>(a, out);

    // smem: 52800 KV + 1600 att + 256 mh + 8 candv + 8 candn + 8 candj
    //       + 200 idxs + 2 icur + 200 visd = 55082 floats = 220328 B
    const int smem_bytes = 55082 * 4;
    (void)cudaFuncSetAttribute(decode_kernel, cudaFuncAttributeMaxDynamicSharedMemorySize, smem_bytes);

    for (int c0 = 0; c0 < a.batch; c0 += CH){
        const int cb = (a.batch - c0 < CH) ? (a.batch - c0) : CH;
        dim3 g(cb, 4);
        gemm_kernel<<<g, 256>>>(a, c0);
        const int nb = (cb + 1) / 2;
        decode_kernel<<<nb, 256, smem_bytes>>>(a, c0, cb, out);
    }
}